// round 1
// baseline (speedup 1.0000x reference)
#include <cuda_runtime.h>
#include <cuda_bf16.h>
#include <float.h>

#define W 128
#define BINS 50
#define NBOUND (BINS - 1)   // 49 inner boundaries
#define THREADS 256

__global__ __launch_bounds__(THREADS, 8)
void mtf_kernel(const float* __restrict__ X, float* __restrict__ out, int S) {
    __shared__ float bnd[NBOUND];
    __shared__ int   bins[W];
    __shared__ float mtm[BINS * BINS];
    __shared__ float smn[8], smx[8];
    __shared__ float bmn, bmx;
    __shared__ float rowinv[BINS];

    const int s   = blockIdx.x;
    const int tid = threadIdx.x;
    const int lane = tid & 31;
    const int wid  = tid >> 5;

    if (s >= S) return;

    const float* x = X + (size_t)s * W;

    // Boundaries: linspace(-1, 1, 51)[1:-1]. Computed in double then rounded,
    // matching lo + i*(hi-lo)/num to within an ulp (ties measure-zero on
    // continuous data).
    if (tid < NBOUND) {
        bnd[tid] = (float)(-1.0 + (2.0 * (double)(tid + 1)) / 50.0);
    }

    // Zero the transition matrix (2500 floats).
    for (int i = tid; i < BINS * BINS; i += THREADS) mtm[i] = 0.0f;

    // Load series value (threads 0..127).
    float v = 0.0f;
    if (tid < W) v = x[tid];

    // --- block min/max reduction over the 128 values ---
    float mn = (tid < W) ? v : FLT_MAX;
    float mx = (tid < W) ? v : -FLT_MAX;
    #pragma unroll
    for (int o = 16; o > 0; o >>= 1) {
        mn = fminf(mn, __shfl_xor_sync(0xFFFFFFFFu, mn, o));
        mx = fmaxf(mx, __shfl_xor_sync(0xFFFFFFFFu, mx, o));
    }
    if (lane == 0) { smn[wid] = mn; smx[wid] = mx; }
    __syncthreads();
    if (wid == 0) {
        float a = (lane < 8) ? smn[lane] : FLT_MAX;
        float b = (lane < 8) ? smx[lane] : -FLT_MAX;
        #pragma unroll
        for (int o = 4; o > 0; o >>= 1) {
            a = fminf(a, __shfl_xor_sync(0xFFFFFFFFu, a, o));
            b = fmaxf(b, __shfl_xor_sync(0xFFFFFFFFu, b, o));
        }
        if (lane == 0) { bmn = a; bmx = b; }
    }
    __syncthreads();

    // --- scale into [-1, 1] (same op order as reference) and bucketize ---
    if (tid < W) {
        float denom = bmx - bmn + 1e-6f;
        float t = (v - bmn) / denom;
        float xsc = t * 2.0f + (-1.0f);   // t*(hi-lo) + lo
        // searchsorted(boundaries, xsc, side='left') == #{k : bnd[k] < xsc}
        int cnt = 0;
        #pragma unroll
        for (int k = 0; k < NBOUND; k++) cnt += (bnd[k] < xsc) ? 1 : 0;
        bins[tid] = cnt;
    }
    __syncthreads();

    // --- transition histogram: mtm[bin[t], bin[t+1]] += 1 ---
    if (tid < W - 1) {
        atomicAdd(&mtm[bins[tid] * BINS + bins[tid + 1]], 1.0f);
    }
    __syncthreads();

    // --- row sums -> reciprocals (empty rows -> divide by 1) ---
    if (tid < BINS) {
        float sum = 0.0f;
        const float* row = &mtm[tid * BINS];
        #pragma unroll
        for (int k = 0; k < BINS; k++) sum += row[k];
        rowinv[tid] = (sum == 0.0f) ? 1.0f : (1.0f / sum);
    }
    __syncthreads();

    // --- normalize in place ---
    for (int i = tid; i < BINS * BINS; i += THREADS) {
        mtm[i] *= rowinv[i / BINS];
    }
    __syncthreads();

    // --- final gather: out[t1, t2] = mtm[bin[t1], bin[t2]], float4 stores ---
    float* o = out + (size_t)s * W * W;
    for (int i = tid * 4; i < W * W; i += THREADS * 4) {
        int t1 = i >> 7;
        int t2 = i & (W - 1);
        const float* row = &mtm[bins[t1] * BINS];
        float4 val;
        val.x = row[bins[t2 + 0]];
        val.y = row[bins[t2 + 1]];
        val.z = row[bins[t2 + 2]];
        val.w = row[bins[t2 + 3]];
        *reinterpret_cast<float4*>(o + i) = val;
    }
}

extern "C" void kernel_launch(void* const* d_in, const int* in_sizes, int n_in,
                              void* d_out, int out_size) {
    const float* X = (const float*)d_in[0];
    float* out = (float*)d_out;
    int S = in_sizes[0] / W;   // 256*6 = 1536 series
    mtf_kernel<<<S, THREADS>>>(X, out, S);
}